// round 14
// baseline (speedup 1.0000x reference)
#include <cuda_runtime.h>
#include <cuda_fp16.h>
#include <cstdint>

// Problem constants
#define BATCH 2
#define SEQ   2048
#define DMODEL 1024
#define NHEAD 16
#define HDIM  64
#define BH    (BATCH*NHEAD)          // 32
#define MROWS (BATCH*SEQ)            // 4096

// Scratch (device globals: allocation-free per harness rules)
__device__ __half g_x[MROWS * DMODEL];
__device__ __half g_wqkv[DMODEL * 3 * DMODEL];
__device__ __half g_wproj[DMODEL * DMODEL];
__device__ __half g_q[BH * SEQ * HDIM];        // [bh][s][hd]
__device__ __half g_k[BH * SEQ * HDIM];
__device__ __half g_v[BH * SEQ * HDIM];
__device__ __half g_ctx[MROWS * DMODEL];       // [b*S+s][d]

// ---------------------------------------------------------------------------
// helpers
// ---------------------------------------------------------------------------
__device__ __forceinline__ uint32_t cvt2h(float lo, float hi) {  // pack f16x2
    uint32_t d;
    asm("cvt.rn.f16x2.f32 %0, %1, %2;" : "=r"(d) : "f"(hi), "f"(lo));
    return d;
}
__device__ __forceinline__ float ex2f(float x) {       // 2^x via MUFU
    float r;
    asm("ex2.approx.f32 %0, %1;" : "=f"(r) : "f"(x));
    return r;
}
__device__ __forceinline__ uint32_t smaddr(const void* p) {
    uint32_t a;
    asm("{ .reg .u64 t; cvta.to.shared.u64 t, %1; cvt.u32.u64 %0, t; }"
        : "=r"(a) : "l"(p));
    return a;
}

// async 16B copy gmem -> smem
__device__ __forceinline__ void cp16(void* smem_dst, const void* gsrc) {
    uint32_t d = smaddr(smem_dst);
    asm volatile("cp.async.cg.shared.global [%0], [%1], 16;" :: "r"(d), "l"(gsrc));
}
#define CP_COMMIT() asm volatile("cp.async.commit_group;" ::: "memory")
#define CP_WAIT1()  asm volatile("cp.async.wait_group 1;" ::: "memory")
#define CP_WAIT0()  asm volatile("cp.async.wait_group 0;" ::: "memory")

__device__ __forceinline__ void ldm4(uint32_t* r, uint32_t a) {
    asm volatile("ldmatrix.sync.aligned.m8n8.x4.shared.b16 {%0,%1,%2,%3}, [%4];"
        : "=r"(r[0]), "=r"(r[1]), "=r"(r[2]), "=r"(r[3]) : "r"(a));
}
__device__ __forceinline__ void ldm4t(uint32_t* r, uint32_t a) {
    asm volatile("ldmatrix.sync.aligned.m8n8.x4.trans.shared.b16 {%0,%1,%2,%3}, [%4];"
        : "=r"(r[0]), "=r"(r[1]), "=r"(r[2]), "=r"(r[3]) : "r"(a));
}

// mma m16n8k16 f16 inputs, f32 accum; D += A*B (C aliased to D)
__device__ __forceinline__ void mma16(float* d, const uint32_t* a, const uint32_t* b) {
    asm volatile(
        "mma.sync.aligned.m16n8k16.row.col.f32.f16.f16.f32 "
        "{%0,%1,%2,%3}, {%4,%5,%6,%7}, {%8,%9}, {%0,%1,%2,%3};\n"
        : "+f"(d[0]), "+f"(d[1]), "+f"(d[2]), "+f"(d[3])
        : "r"(a[0]), "r"(a[1]), "r"(a[2]), "r"(a[3]), "r"(b[0]), "r"(b[1]));
}

// ---------------------------------------------------------------------------
// f32 -> f16 pre-convert: all three inputs in ONE launch (grid-stride)
// ---------------------------------------------------------------------------
__global__ void to_half3_kernel(const float4* __restrict__ x,   uint2* __restrict__ xo,   int nx,
                                const float4* __restrict__ w1,  uint2* __restrict__ w1o,  int n1,
                                const float4* __restrict__ w2,  uint2* __restrict__ w2o,  int n2)
{
    const int stride = gridDim.x * blockDim.x;
    int i0 = blockIdx.x * blockDim.x + threadIdx.x;
    for (int i = i0; i < nx; i += stride) {
        float4 v = x[i];  uint2 o = { cvt2h(v.x, v.y), cvt2h(v.z, v.w) };  xo[i] = o;
    }
    for (int i = i0; i < n1; i += stride) {
        float4 v = w1[i]; uint2 o = { cvt2h(v.x, v.y), cvt2h(v.z, v.w) };  w1o[i] = o;
    }
    for (int i = i0; i < n2; i += stride) {
        float4 v = w2[i]; uint2 o = { cvt2h(v.x, v.y), cvt2h(v.z, v.w) };  w2o[i] = o;
    }
}

// ---------------------------------------------------------------------------
// fp16 mma.sync GEMM: C[M,N] = A[M,K] @ B[K,N] + bias (f32 accum).
// CTA tile 128x64, 128 threads (4 warps, 2m x 2n), warp tile 64x32, BK=32.
// 3-stage cp.async ring; low-register config -> 3 CTAs/SM (12 warps/SM).
// mode 0: write C f32 ; mode 1: scatter f16 q/k/v (QKV head layout)
// ---------------------------------------------------------------------------
#define GA_ST 40                               // A row stride (halfs, K=32+pad)
#define GB_ST 72                               // B row stride (halfs, N=64+pad)
#define G_STGH (128*GA_ST + 32*GB_ST)          // 7424 halfs per stage
#define GEMM_SMEM (3 * G_STGH * 2)             // 44,544 B

__device__ __forceinline__ void gemm_stage_async(
    __half* sm, int s, const __half* __restrict__ A, const __half* __restrict__ Bm,
    int m0, int n0, int kt, int K, int N, int tid)
{
    __half* As = sm + s * G_STGH;
    __half* Bs = As + 128 * GA_ST;
#pragma unroll
    for (int i = 0; i < 4; i++) {              // A: 512 granules of 8 halfs
        int f = tid + i * 128;
        int row = f >> 2, c0 = (f & 3) * 8;
        cp16(&As[row * GA_ST + c0], A + (size_t)(m0 + row) * K + kt + c0);
    }
#pragma unroll
    for (int i = 0; i < 2; i++) {              // B: 256 granules
        int f = tid + i * 128;
        int row = f >> 3, c0 = (f & 7) * 8;
        cp16(&Bs[row * GB_ST + c0], Bm + (size_t)(kt + row) * N + n0 + c0);
    }
}

__global__ __launch_bounds__(128, 3) void gemm_tc(
    const __half* __restrict__ A, const __half* __restrict__ Bm,
    const float* __restrict__ bias, float* __restrict__ C,
    int M, int N, int K, int mode)
{
    extern __shared__ __half smh[];

    const int tid  = threadIdx.x;
    const int wid  = tid >> 5;
    const int lane = tid & 31;
    const int g = lane >> 2, t = lane & 3;
    const int wm = wid >> 1, wn = wid & 1;
    const int m0 = blockIdx.y * 128;
    const int n0 = blockIdx.x * 64;

    // lane-dependent ldmatrix offsets (halfs)
    const int aLane = ((lane & 7) + ((lane >> 3) & 1) * 8) * GA_ST + (lane >> 4) * 8;
    const int bLane = ((lane & 7) + ((lane >> 3) & 1) * 8) * GB_ST + (lane >> 4) * 8;

    float acc[4][4][4];                        // warp tile 64x32
#pragma unroll
    for (int mt = 0; mt < 4; mt++)
#pragma unroll
        for (int nt = 0; nt < 4; nt++)
#pragma unroll
            for (int j = 0; j < 4; j++) acc[mt][nt][j] = 0.f;

    const int T = K / 32;   // 32
    gemm_stage_async(smh, 0, A, Bm, m0, n0, 0, K, N, tid);
    CP_COMMIT();
    gemm_stage_async(smh, 1, A, Bm, m0, n0, 32, K, N, tid);
    CP_COMMIT();

    for (int tt = 0; tt < T; tt++) {
        if (tt + 2 < T) CP_WAIT1(); else CP_WAIT0();
        __syncthreads();
        if (tt + 2 < T) {
            gemm_stage_async(smh, (tt + 2) % 3, A, Bm, m0, n0, (tt + 2) * 32, K, N, tid);
            CP_COMMIT();
        }
        const __half* As = smh + (tt % 3) * G_STGH;
        const __half* Bs = As + 128 * GA_ST;
        const uint32_t sa = smaddr(As);
        const uint32_t sb = smaddr(Bs);
#pragma unroll
        for (int kk = 0; kk < 2; kk++) {
            uint32_t av[4][4];
#pragma unroll
            for (int mt = 0; mt < 4; mt++)
                ldm4(av[mt], sa + 2 * ((wm * 64 + mt * 16) * GA_ST + kk * 16 + aLane));
            uint32_t bv[2][4];                 // [pair][4 regs] -> 2 n8 frags each
#pragma unroll
            for (int p = 0; p < 2; p++)
                ldm4t(bv[p], sb + 2 * (kk * 16 * GB_ST + wn * 32 + p * 16 + bLane));
#pragma unroll
            for (int mt = 0; mt < 4; mt++)
#pragma unroll
                for (int p = 0; p < 2; p++) {
                    mma16(acc[mt][2 * p],     av[mt], &bv[p][0]);
                    mma16(acc[mt][2 * p + 1], av[mt], &bv[p][2]);
                }
        }
    }

    // epilogue
#pragma unroll
    for (int mt = 0; mt < 4; mt++) {
        int r0 = m0 + wm * 64 + mt * 16 + g;
        int r1 = r0 + 8;
#pragma unroll
        for (int nt = 0; nt < 4; nt++) {
            int col = n0 + wn * 32 + nt * 8 + 2 * t;
            float2 b2 = *(const float2*)(bias + col);
            if (mode == 0) {
                float2 v0 = { acc[mt][nt][0] + b2.x, acc[mt][nt][1] + b2.y };
                float2 v1 = { acc[mt][nt][2] + b2.x, acc[mt][nt][3] + b2.y };
                *(float2*)(C + (size_t)r0 * N + col) = v0;
                *(float2*)(C + (size_t)r1 * N + col) = v1;
            } else {
                uint32_t h0 = cvt2h(acc[mt][nt][0] + b2.x, acc[mt][nt][1] + b2.y);
                uint32_t h1 = cvt2h(acc[mt][nt][2] + b2.x, acc[mt][nt][3] + b2.y);
                int part = col >> 10;
                int rr   = col & 1023;
                int h    = rr >> 6;
                int hd   = rr & 63;
                __half* dst = (part == 0) ? g_q : (part == 1) ? g_k : g_v;
                int b0i = r0 >> 11, s0 = r0 & 2047;
                int b1i = r1 >> 11, s1 = r1 & 2047;
                *(uint32_t*)(dst + ((size_t)(b0i * NHEAD + h) * SEQ + s0) * HDIM + hd) = h0;
                *(uint32_t*)(dst + ((size_t)(b1i * NHEAD + h) * SEQ + s1) * HDIM + hd) = h1;
            }
        }
    }
}

// ---------------------------------------------------------------------------
// fp16 tensor-core causal flash attention (round-11 proven version).
// CTA: 128 threads (4 warps), BM=128, 32 rows/warp (2 m16 halves), BN=64.
// 2-stage KV ring; K/V fragments shared across both m-halves;
// P converted in-register (no smem round-trip).
// ---------------------------------------------------------------------------
#define AQ_ST 72                               // row stride (halfs)
#define ATT_QH  (128 * AQ_ST)
#define ATT_KVH (2 * 64 * AQ_ST)
#define ATT_SMEM ((ATT_QH + 2 * ATT_KVH) * 2)  // 55,296 B

__device__ __forceinline__ void attn_stage_kv_async(
    __half* base, int s, const __half* __restrict__ kbp, const __half* __restrict__ vbp,
    int kb, int tid)
{
    __half* Ks = base + ATT_QH + s * ATT_KVH;
    __half* Vs = Ks + 64 * AQ_ST;
#pragma unroll
    for (int i = 0; i < 4; i++) {
        int f = tid + i * 128;
        int row = f >> 3, c0 = (f & 7) * 8;
        cp16(&Ks[row * AQ_ST + c0], kbp + (size_t)(kb + row) * HDIM + c0);
        cp16(&Vs[row * AQ_ST + c0], vbp + (size_t)(kb + row) * HDIM + c0);
    }
}

__global__ __launch_bounds__(128, 2) void attn_tc()
{
    extern __shared__ __half smh[];
    __half* Qs = smh;

    const int tid  = threadIdx.x;
    const int wid  = tid >> 5;
    const int lane = tid & 31;
    const int g = lane >> 2, t = lane & 3;
    const int bh = blockIdx.y;
    const int m0 = ((int)gridDim.x - 1 - (int)blockIdx.x) * 128;  // heavy first

    const __half* qb  = g_q + (size_t)bh * SEQ * HDIM;
    const __half* kbp = g_k + (size_t)bh * SEQ * HDIM;
    const __half* vbp = g_v + (size_t)bh * SEQ * HDIM;

    const int ntile = m0 / 64 + 2;
    const int rb = wid * 32;

    // lane-dependent ldmatrix offsets (halfs)
    const int qLane = ((lane & 7) + ((lane >> 3) & 1) * 8) * AQ_ST + (lane >> 4) * 8;
    const int kLane = ((lane & 7) + (lane >> 4) * 8) * AQ_ST + ((lane >> 3) & 1) * 8;
    const int vLane = qLane;

    // prologue: Q + KV tile0 in group 0, KV tile1 in group 1
#pragma unroll
    for (int i = 0; i < 8; i++) {
        int f = tid + i * 128;
        int row = f >> 3, c0 = (f & 7) * 8;
        cp16(&Qs[row * AQ_ST + c0], qb + (size_t)(m0 + row) * HDIM + c0);
    }
    attn_stage_kv_async(smh, 0, kbp, vbp, 0, tid);
    CP_COMMIT();
    attn_stage_kv_async(smh, 1, kbp, vbp, 64, tid);
    CP_COMMIT();
    CP_WAIT1();
    __syncthreads();

    // Q fragments: [mh][kk][4]
    uint32_t qa[2][4][4];
    {
        const uint32_t sq = smaddr(Qs);
#pragma unroll
        for (int mh = 0; mh < 2; mh++)
#pragma unroll
            for (int kk = 0; kk < 4; kk++)
                ldm4(qa[mh][kk], sq + 2 * ((rb + mh * 16) * AQ_ST + kk * 16 + qLane));
    }

    float o[2][8][4];
#pragma unroll
    for (int mh = 0; mh < 2; mh++)
#pragma unroll
        for (int nt = 0; nt < 8; nt++)
#pragma unroll
            for (int j = 0; j < 4; j++) o[mh][nt][j] = 0.f;
    float mm[2][2] = { {-1e30f, -1e30f}, {-1e30f, -1e30f} };
    float ll[2][2] = { {0.f, 0.f}, {0.f, 0.f} };

    const float SC = 0.125f * 1.44269504f;     // score scale, base-2 domain

    for (int tt = 0; tt < ntile; tt++) {
        const int kb = tt * 64;
        const __half* Kc = smh + ATT_QH + (tt & 1) * ATT_KVH;
        const __half* Vc = Kc + 64 * AQ_ST;

        if (kb <= m0 + rb + 31) {
            const uint32_t sk = smaddr(Kc);
            const uint32_t sv = smaddr(Vc);

            // S = Q @ K^T (warp: 32 x 64)
            float s[2][8][4];
#pragma unroll
            for (int mh = 0; mh < 2; mh++)
#pragma unroll
                for (int nt = 0; nt < 8; nt++)
#pragma unroll
                    for (int j = 0; j < 4; j++) s[mh][nt][j] = 0.f;
#pragma unroll
            for (int kk = 0; kk < 4; kk++) {
#pragma unroll
                for (int p = 0; p < 4; p++) {
                    uint32_t r[4];
                    ldm4(r, sk + 2 * (p * 16 * AQ_ST + kk * 16 + kLane));
                    mma16(s[0][2 * p],     qa[0][kk], &r[0]);
                    mma16(s[0][2 * p + 1], qa[0][kk], &r[2]);
                    mma16(s[1][2 * p],     qa[1][kk], &r[0]);
                    mma16(s[1][2 * p + 1], qa[1][kk], &r[2]);
                }
            }

            // softmax per m-half
#pragma unroll
            for (int mh = 0; mh < 2; mh++) {
                const int rlo = m0 + rb + mh * 16 + g;
                const int rhi = rlo + 8;
                if (kb + 63 > m0 + rb + mh * 16) {
#pragma unroll
                    for (int nt = 0; nt < 8; nt++) {
                        int c0 = kb + nt * 8 + 2 * t;
                        s[mh][nt][0] = (c0     > rlo) ? -1e30f : s[mh][nt][0] * SC;
                        s[mh][nt][1] = (c0 + 1 > rlo) ? -1e30f : s[mh][nt][1] * SC;
                        s[mh][nt][2] = (c0     > rhi) ? -1e30f : s[mh][nt][2] * SC;
                        s[mh][nt][3] = (c0 + 1 > rhi) ? -1e30f : s[mh][nt][3] * SC;
                    }
                } else {
#pragma unroll
                    for (int nt = 0; nt < 8; nt++)
#pragma unroll
                        for (int j = 0; j < 4; j++) s[mh][nt][j] *= SC;
                }

                float tlo = -1e30f, thi = -1e30f;
#pragma unroll
                for (int nt = 0; nt < 8; nt++) {
                    tlo = fmaxf(tlo, fmaxf(s[mh][nt][0], s[mh][nt][1]));
                    thi = fmaxf(thi, fmaxf(s[mh][nt][2], s[mh][nt][3]));
                }
                tlo = fmaxf(tlo, __shfl_xor_sync(0xffffffff, tlo, 1));
                tlo = fmaxf(tlo, __shfl_xor_sync(0xffffffff, tlo, 2));
                thi = fmaxf(thi, __shfl_xor_sync(0xffffffff, thi, 1));
                thi = fmaxf(thi, __shfl_xor_sync(0xffffffff, thi, 2));

                float nmlo = fmaxf(mm[mh][0], tlo), nmhi = fmaxf(mm[mh][1], thi);
                float alo = ex2f(mm[mh][0] - nmlo), ahi = ex2f(mm[mh][1] - nmhi);
                mm[mh][0] = nmlo; mm[mh][1] = nmhi;

                float slo = 0.f, shi = 0.f;
#pragma unroll
                for (int nt = 0; nt < 8; nt++) {
                    s[mh][nt][0] = ex2f(s[mh][nt][0] - nmlo);
                    s[mh][nt][1] = ex2f(s[mh][nt][1] - nmlo);
                    s[mh][nt][2] = ex2f(s[mh][nt][2] - nmhi);
                    s[mh][nt][3] = ex2f(s[mh][nt][3] - nmhi);
                    slo += s[mh][nt][0] + s[mh][nt][1];
                    shi += s[mh][nt][2] + s[mh][nt][3];
                }
                slo += __shfl_xor_sync(0xffffffff, slo, 1);
                slo += __shfl_xor_sync(0xffffffff, slo, 2);
                shi += __shfl_xor_sync(0xffffffff, shi, 1);
                shi += __shfl_xor_sync(0xffffffff, shi, 2);
                ll[mh][0] = ll[mh][0] * alo + slo;
                ll[mh][1] = ll[mh][1] * ahi + shi;

#pragma unroll
                for (int nt = 0; nt < 8; nt++) {
                    o[mh][nt][0] *= alo; o[mh][nt][1] *= alo;
                    o[mh][nt][2] *= ahi; o[mh][nt][3] *= ahi;
                }
            }

            // O += P @ V  (P converted in-register; V frag shared)
#pragma unroll
            for (int kk = 0; kk < 4; kk++) {
                uint32_t pa0[4], pa1[4];
                pa0[0] = cvt2h(s[0][2*kk][0],   s[0][2*kk][1]);
                pa0[1] = cvt2h(s[0][2*kk][2],   s[0][2*kk][3]);
                pa0[2] = cvt2h(s[0][2*kk+1][0], s[0][2*kk+1][1]);
                pa0[3] = cvt2h(s[0][2*kk+1][2], s[0][2*kk+1][3]);
                pa1[0] = cvt2h(s[1][2*kk][0],   s[1][2*kk][1]);
                pa1[1] = cvt2h(s[1][2*kk][2],   s[1][2*kk][3]);
                pa1[2] = cvt2h(s[1][2*kk+1][0], s[1][2*kk+1][1]);
                pa1[3] = cvt2h(s[1][2*kk+1][2], s[1][2*kk+1][3]);
#pragma unroll
                for (int p = 0; p < 4; p++) {
                    uint32_t r[4];
                    ldm4t(r, sv + 2 * (kk * 16 * AQ_ST + p * 16 + vLane));
                    mma16(o[0][2 * p],     pa0, &r[0]);
                    mma16(o[0][2 * p + 1], pa0, &r[2]);
                    mma16(o[1][2 * p],     pa1, &r[0]);
                    mma16(o[1][2 * p + 1], pa1, &r[2]);
                }
            }
        }

        __syncthreads();
        if (tt + 2 < ntile) {
            attn_stage_kv_async(smh, tt & 1, kbp, vbp, (tt + 2) * 64, tid);
            CP_COMMIT();
            CP_WAIT1();
        } else {
            CP_WAIT0();
        }
        __syncthreads();
    }

    // epilogue: O /= l, f16, write to ctx (feeds fp16 proj GEMM)
    const int bidx = bh >> 4, h = bh & 15;
#pragma unroll
    for (int mh = 0; mh < 2; mh++) {
        const float ilo = 1.f / ll[mh][0], ihi = 1.f / ll[mh][1];
        const int rlo = m0 + rb + mh * 16 + g;
        const int rhi = rlo + 8;
        __half* clo = g_ctx + ((size_t)(bidx * SEQ + rlo)) * DMODEL + h * HDIM;
        __half* chi = g_ctx + ((size_t)(bidx * SEQ + rhi)) * DMODEL + h * HDIM;
#pragma unroll
        for (int nt = 0; nt < 8; nt++) {
            int c = nt * 8 + 2 * t;
            *(uint32_t*)(clo + c) = cvt2h(o[mh][nt][0] * ilo, o[mh][nt][1] * ilo);
            *(uint32_t*)(chi + c) = cvt2h(o[mh][nt][2] * ihi, o[mh][nt][3] * ihi);
        }
    }
}

// ---------------------------------------------------------------------------
extern "C" void kernel_launch(void* const* d_in, const int* in_sizes, int n_in,
                              void* d_out, int out_size)
{
    const float* x      = (const float*)d_in[0];   // [B,S,D]
    const float* w_qkv  = (const float*)d_in[1];   // [D, 3D]
    const float* b_qkv  = (const float*)d_in[2];   // [3D]
    const float* w_proj = (const float*)d_in[3];   // [D, D]
    const float* b_proj = (const float*)d_in[4];   // [D]
    float* out = (float*)d_out;                    // [B,S,D]

    __half *xh, *wqkvh, *wprojh, *ctxh;
    cudaGetSymbolAddress((void**)&xh, g_x);
    cudaGetSymbolAddress((void**)&wqkvh, g_wqkv);
    cudaGetSymbolAddress((void**)&wprojh, g_wproj);
    cudaGetSymbolAddress((void**)&ctxh, g_ctx);

    cudaFuncSetAttribute(gemm_tc, cudaFuncAttributeMaxDynamicSharedMemorySize, GEMM_SMEM);
    cudaFuncSetAttribute(attn_tc, cudaFuncAttributeMaxDynamicSharedMemorySize, ATT_SMEM);

    // 0) pre-convert all inputs to fp16 (one launch)
    to_half3_kernel<<<1184, 256>>>(
        (const float4*)x, (uint2*)xh, MROWS * DMODEL / 4,
        (const float4*)w_qkv, (uint2*)wqkvh, DMODEL * 3 * DMODEL / 4,
        (const float4*)w_proj, (uint2*)wprojh, DMODEL * DMODEL / 4);

    // 1) QKV projection -> g_q/g_k/g_v (fp16)
    {
        dim3 grid(3 * DMODEL / 64, MROWS / 128);   // (48, 32)
        gemm_tc<<<grid, 128, GEMM_SMEM>>>(xh, wqkvh, b_qkv, nullptr,
                                          MROWS, 3 * DMODEL, DMODEL, /*mode=*/1);
    }
    // 2) causal attention -> g_ctx (fp16)
    {
        dim3 grid(SEQ / 128, BH);                  // (16, 32)
        attn_tc<<<grid, 128, ATT_SMEM>>>();
    }
    // 3) output projection -> d_out (f32)
    {
        dim3 grid(DMODEL / 64, MROWS / 128);       // (16, 32)
        gemm_tc<<<grid, 128, GEMM_SMEM>>>(ctxh, wprojh, b_proj, out,
                                          MROWS, DMODEL, DMODEL, /*mode=*/0);
    }
    (void)in_sizes; (void)n_in; (void)out_size;
}

// round 15
// speedup vs baseline: 1.0290x; 1.0290x over previous
#include <cuda_runtime.h>
#include <cuda_fp16.h>
#include <cstdint>

// Problem constants
#define BATCH 2
#define SEQ   2048
#define DMODEL 1024
#define NHEAD 16
#define HDIM  64
#define BH    (BATCH*NHEAD)          // 32
#define MROWS (BATCH*SEQ)            // 4096

// Scratch (device globals: allocation-free per harness rules)
__device__ __half g_x[MROWS * DMODEL];
__device__ __half g_wqkv[DMODEL * 3 * DMODEL];
__device__ __half g_wproj[DMODEL * DMODEL];
__device__ __half g_q[BH * SEQ * HDIM];        // [bh][s][hd]
__device__ __half g_k[BH * SEQ * HDIM];
__device__ __half g_v[BH * SEQ * HDIM];
__device__ __half g_ctx[MROWS * DMODEL];       // [b*S+s][d]

// ---------------------------------------------------------------------------
// helpers
// ---------------------------------------------------------------------------
__device__ __forceinline__ uint32_t cvt2h(float lo, float hi) {  // pack f16x2
    uint32_t d;
    asm("cvt.rn.f16x2.f32 %0, %1, %2;" : "=r"(d) : "f"(hi), "f"(lo));
    return d;
}
__device__ __forceinline__ float ex2f(float x) {       // 2^x via MUFU
    float r;
    asm("ex2.approx.f32 %0, %1;" : "=f"(r) : "f"(x));
    return r;
}
__device__ __forceinline__ uint32_t smaddr(const void* p) {
    uint32_t a;
    asm("{ .reg .u64 t; cvta.to.shared.u64 t, %1; cvt.u32.u64 %0, t; }"
        : "=r"(a) : "l"(p));
    return a;
}

// async 16B copy gmem -> smem
__device__ __forceinline__ void cp16(void* smem_dst, const void* gsrc) {
    uint32_t d = smaddr(smem_dst);
    asm volatile("cp.async.cg.shared.global [%0], [%1], 16;" :: "r"(d), "l"(gsrc));
}
#define CP_COMMIT() asm volatile("cp.async.commit_group;" ::: "memory")
#define CP_WAIT1()  asm volatile("cp.async.wait_group 1;" ::: "memory")
#define CP_WAIT0()  asm volatile("cp.async.wait_group 0;" ::: "memory")

__device__ __forceinline__ void ldm4(uint32_t* r, uint32_t a) {
    asm volatile("ldmatrix.sync.aligned.m8n8.x4.shared.b16 {%0,%1,%2,%3}, [%4];"
        : "=r"(r[0]), "=r"(r[1]), "=r"(r[2]), "=r"(r[3]) : "r"(a));
}
__device__ __forceinline__ void ldm4t(uint32_t* r, uint32_t a) {
    asm volatile("ldmatrix.sync.aligned.m8n8.x4.trans.shared.b16 {%0,%1,%2,%3}, [%4];"
        : "=r"(r[0]), "=r"(r[1]), "=r"(r[2]), "=r"(r[3]) : "r"(a));
}

// mma m16n8k16 f16 inputs, f32 accum; D += A*B (C aliased to D)
__device__ __forceinline__ void mma16(float* d, const uint32_t* a, const uint32_t* b) {
    asm volatile(
        "mma.sync.aligned.m16n8k16.row.col.f32.f16.f16.f32 "
        "{%0,%1,%2,%3}, {%4,%5,%6,%7}, {%8,%9}, {%0,%1,%2,%3};\n"
        : "+f"(d[0]), "+f"(d[1]), "+f"(d[2]), "+f"(d[3])
        : "r"(a[0]), "r"(a[1]), "r"(a[2]), "r"(a[3]), "r"(b[0]), "r"(b[1]));
}

// ---------------------------------------------------------------------------
// f32 -> f16 pre-convert: all three inputs in ONE launch (grid-stride)
// ---------------------------------------------------------------------------
__global__ void to_half3_kernel(const float4* __restrict__ x,   uint2* __restrict__ xo,   int nx,
                                const float4* __restrict__ w1,  uint2* __restrict__ w1o,  int n1,
                                const float4* __restrict__ w2,  uint2* __restrict__ w2o,  int n2)
{
    const int stride = gridDim.x * blockDim.x;
    int i0 = blockIdx.x * blockDim.x + threadIdx.x;
    for (int i = i0; i < nx; i += stride) {
        float4 v = x[i];  uint2 o = { cvt2h(v.x, v.y), cvt2h(v.z, v.w) };  xo[i] = o;
    }
    for (int i = i0; i < n1; i += stride) {
        float4 v = w1[i]; uint2 o = { cvt2h(v.x, v.y), cvt2h(v.z, v.w) };  w1o[i] = o;
    }
    for (int i = i0; i < n2; i += stride) {
        float4 v = w2[i]; uint2 o = { cvt2h(v.x, v.y), cvt2h(v.z, v.w) };  w2o[i] = o;
    }
}

// ---------------------------------------------------------------------------
// fp16 mma.sync GEMM: C[M,N] = A[M,K] @ B[K,N] + bias (f32 accum).
// Tile 128x128x64, 128 threads (4 warps, 2m x 2n), warp tile 64x64.
// 3-stage cp.async ring. Fragment prefetch: all B-frags hoisted to tile top,
// A-frags double-buffered across kk -> ldmatrix latency hidden by HMMA issue.
// mode 0: write C f32 ; mode 1: scatter f16 q/k/v (QKV head layout)
// ---------------------------------------------------------------------------
#define GA_ST 72                               // A row stride (halfs)
#define GB_ST 136                              // B row stride (halfs)
#define G_STGH (128*GA_ST + 64*GB_ST)          // 17920 halfs per stage
#define GEMM_SMEM (3 * G_STGH * 2)             // 107,520 B

__device__ __forceinline__ void gemm_stage_async(
    __half* sm, int s, const __half* __restrict__ A, const __half* __restrict__ Bm,
    int m0, int n0, int kt, int K, int N, int tid)
{
    __half* As = sm + s * G_STGH;
    __half* Bs = As + 128 * GA_ST;
#pragma unroll
    for (int i = 0; i < 8; i++) {              // A: 1024 granules of 8 halfs
        int f = tid + i * 128;
        int row = f >> 3, c0 = (f & 7) * 8;
        cp16(&As[row * GA_ST + c0], A + (size_t)(m0 + row) * K + kt + c0);
    }
#pragma unroll
    for (int i = 0; i < 8; i++) {              // B: 1024 granules
        int f = tid + i * 128;
        int row = f >> 4, c0 = (f & 15) * 8;
        cp16(&Bs[row * GB_ST + c0], Bm + (size_t)(kt + row) * N + n0 + c0);
    }
}

__global__ __launch_bounds__(128, 2) void gemm_tc(
    const __half* __restrict__ A, const __half* __restrict__ Bm,
    const float* __restrict__ bias, float* __restrict__ C,
    int M, int N, int K, int mode)
{
    extern __shared__ __half smh[];

    const int tid  = threadIdx.x;
    const int wid  = tid >> 5;
    const int lane = tid & 31;
    const int g = lane >> 2, t = lane & 3;
    const int wm = wid >> 1, wn = wid & 1;
    const int m0 = blockIdx.y * 128;
    const int n0 = blockIdx.x * 128;

    // lane-dependent ldmatrix offsets (halfs)
    const int aLane = ((lane & 7) + ((lane >> 3) & 1) * 8) * GA_ST + (lane >> 4) * 8;
    const int bLane = ((lane & 7) + ((lane >> 3) & 1) * 8) * GB_ST + (lane >> 4) * 8;

    float acc[4][8][4];                        // warp tile 64x64 (128 regs)
#pragma unroll
    for (int mt = 0; mt < 4; mt++)
#pragma unroll
        for (int nt = 0; nt < 8; nt++)
#pragma unroll
            for (int j = 0; j < 4; j++) acc[mt][nt][j] = 0.f;

    const int T = K / 64;   // 16
    gemm_stage_async(smh, 0, A, Bm, m0, n0, 0, K, N, tid);
    CP_COMMIT();
    gemm_stage_async(smh, 1, A, Bm, m0, n0, 64, K, N, tid);
    CP_COMMIT();

    for (int tt = 0; tt < T; tt++) {
        if (tt + 2 < T) CP_WAIT1(); else CP_WAIT0();
        __syncthreads();
        if (tt + 2 < T) {
            gemm_stage_async(smh, (tt + 2) % 3, A, Bm, m0, n0, (tt + 2) * 64, K, N, tid);
            CP_COMMIT();
        }
        const __half* As = smh + (tt % 3) * G_STGH;
        const __half* Bs = As + 128 * GA_ST;
        const uint32_t sa = smaddr(As);
        const uint32_t sb = smaddr(Bs);

        // hoist ALL B fragments for this k-tile (16 ldmatrix, 64 regs)
        uint32_t bv[4][4][4];                  // [kk][pair][4]
#pragma unroll
        for (int kk = 0; kk < 4; kk++)
#pragma unroll
            for (int p = 0; p < 4; p++)
                ldm4t(bv[kk][p], sb + 2 * (kk * 16 * GB_ST + wn * 64 + p * 16 + bLane));

        // A fragments double-buffered across kk (2x16 regs)
        uint32_t av[2][4][4];
#pragma unroll
        for (int mt = 0; mt < 4; mt++)
            ldm4(av[0][mt], sa + 2 * ((wm * 64 + mt * 16) * GA_ST + 0 * 16 + aLane));

#pragma unroll
        for (int kk = 0; kk < 4; kk++) {
            if (kk < 3) {
#pragma unroll
                for (int mt = 0; mt < 4; mt++)
                    ldm4(av[(kk + 1) & 1][mt],
                         sa + 2 * ((wm * 64 + mt * 16) * GA_ST + (kk + 1) * 16 + aLane));
            }
#pragma unroll
            for (int mt = 0; mt < 4; mt++)
#pragma unroll
                for (int p = 0; p < 4; p++) {
                    mma16(acc[mt][2 * p],     av[kk & 1][mt], &bv[kk][p][0]);
                    mma16(acc[mt][2 * p + 1], av[kk & 1][mt], &bv[kk][p][2]);
                }
        }
    }

    // epilogue
#pragma unroll
    for (int mt = 0; mt < 4; mt++) {
        int r0 = m0 + wm * 64 + mt * 16 + g;
        int r1 = r0 + 8;
#pragma unroll
        for (int nt = 0; nt < 8; nt++) {
            int col = n0 + wn * 64 + nt * 8 + 2 * t;
            float2 b2 = *(const float2*)(bias + col);
            if (mode == 0) {
                float2 v0 = { acc[mt][nt][0] + b2.x, acc[mt][nt][1] + b2.y };
                float2 v1 = { acc[mt][nt][2] + b2.x, acc[mt][nt][3] + b2.y };
                *(float2*)(C + (size_t)r0 * N + col) = v0;
                *(float2*)(C + (size_t)r1 * N + col) = v1;
            } else {
                uint32_t h0 = cvt2h(acc[mt][nt][0] + b2.x, acc[mt][nt][1] + b2.y);
                uint32_t h1 = cvt2h(acc[mt][nt][2] + b2.x, acc[mt][nt][3] + b2.y);
                int part = col >> 10;
                int rr   = col & 1023;
                int h    = rr >> 6;
                int hd   = rr & 63;
                __half* dst = (part == 0) ? g_q : (part == 1) ? g_k : g_v;
                int b0i = r0 >> 11, s0 = r0 & 2047;
                int b1i = r1 >> 11, s1 = r1 & 2047;
                *(uint32_t*)(dst + ((size_t)(b0i * NHEAD + h) * SEQ + s0) * HDIM + hd) = h0;
                *(uint32_t*)(dst + ((size_t)(b1i * NHEAD + h) * SEQ + s1) * HDIM + hd) = h1;
            }
        }
    }
}

// ---------------------------------------------------------------------------
// fp16 tensor-core causal flash attention (round-11 proven version).
// CTA: 128 threads (4 warps), BM=128, 32 rows/warp (2 m16 halves), BN=64.
// 2-stage KV ring; K/V fragments shared across both m-halves;
// P converted in-register (no smem round-trip).
// ---------------------------------------------------------------------------
#define AQ_ST 72                               // row stride (halfs)
#define ATT_QH  (128 * AQ_ST)
#define ATT_KVH (2 * 64 * AQ_ST)
#define ATT_SMEM ((ATT_QH + 2 * ATT_KVH) * 2)  // 55,296 B

__device__ __forceinline__ void attn_stage_kv_async(
    __half* base, int s, const __half* __restrict__ kbp, const __half* __restrict__ vbp,
    int kb, int tid)
{
    __half* Ks = base + ATT_QH + s * ATT_KVH;
    __half* Vs = Ks + 64 * AQ_ST;
#pragma unroll
    for (int i = 0; i < 4; i++) {
        int f = tid + i * 128;
        int row = f >> 3, c0 = (f & 7) * 8;
        cp16(&Ks[row * AQ_ST + c0], kbp + (size_t)(kb + row) * HDIM + c0);
        cp16(&Vs[row * AQ_ST + c0], vbp + (size_t)(kb + row) * HDIM + c0);
    }
}

__global__ __launch_bounds__(128, 2) void attn_tc()
{
    extern __shared__ __half smh[];
    __half* Qs = smh;

    const int tid  = threadIdx.x;
    const int wid  = tid >> 5;
    const int lane = tid & 31;
    const int g = lane >> 2, t = lane & 3;
    const int bh = blockIdx.y;
    const int m0 = ((int)gridDim.x - 1 - (int)blockIdx.x) * 128;  // heavy first

    const __half* qb  = g_q + (size_t)bh * SEQ * HDIM;
    const __half* kbp = g_k + (size_t)bh * SEQ * HDIM;
    const __half* vbp = g_v + (size_t)bh * SEQ * HDIM;

    const int ntile = m0 / 64 + 2;
    const int rb = wid * 32;

    // lane-dependent ldmatrix offsets (halfs)
    const int qLane = ((lane & 7) + ((lane >> 3) & 1) * 8) * AQ_ST + (lane >> 4) * 8;
    const int kLane = ((lane & 7) + (lane >> 4) * 8) * AQ_ST + ((lane >> 3) & 1) * 8;
    const int vLane = qLane;

    // prologue: Q + KV tile0 in group 0, KV tile1 in group 1
#pragma unroll
    for (int i = 0; i < 8; i++) {
        int f = tid + i * 128;
        int row = f >> 3, c0 = (f & 7) * 8;
        cp16(&Qs[row * AQ_ST + c0], qb + (size_t)(m0 + row) * HDIM + c0);
    }
    attn_stage_kv_async(smh, 0, kbp, vbp, 0, tid);
    CP_COMMIT();
    attn_stage_kv_async(smh, 1, kbp, vbp, 64, tid);
    CP_COMMIT();
    CP_WAIT1();
    __syncthreads();

    // Q fragments: [mh][kk][4]
    uint32_t qa[2][4][4];
    {
        const uint32_t sq = smaddr(Qs);
#pragma unroll
        for (int mh = 0; mh < 2; mh++)
#pragma unroll
            for (int kk = 0; kk < 4; kk++)
                ldm4(qa[mh][kk], sq + 2 * ((rb + mh * 16) * AQ_ST + kk * 16 + qLane));
    }

    float o[2][8][4];
#pragma unroll
    for (int mh = 0; mh < 2; mh++)
#pragma unroll
        for (int nt = 0; nt < 8; nt++)
#pragma unroll
            for (int j = 0; j < 4; j++) o[mh][nt][j] = 0.f;
    float mm[2][2] = { {-1e30f, -1e30f}, {-1e30f, -1e30f} };
    float ll[2][2] = { {0.f, 0.f}, {0.f, 0.f} };

    const float SC = 0.125f * 1.44269504f;     // score scale, base-2 domain

    for (int tt = 0; tt < ntile; tt++) {
        const int kb = tt * 64;
        const __half* Kc = smh + ATT_QH + (tt & 1) * ATT_KVH;
        const __half* Vc = Kc + 64 * AQ_ST;

        if (kb <= m0 + rb + 31) {
            const uint32_t sk = smaddr(Kc);
            const uint32_t sv = smaddr(Vc);

            // S = Q @ K^T (warp: 32 x 64)
            float s[2][8][4];
#pragma unroll
            for (int mh = 0; mh < 2; mh++)
#pragma unroll
                for (int nt = 0; nt < 8; nt++)
#pragma unroll
                    for (int j = 0; j < 4; j++) s[mh][nt][j] = 0.f;
#pragma unroll
            for (int kk = 0; kk < 4; kk++) {
#pragma unroll
                for (int p = 0; p < 4; p++) {
                    uint32_t r[4];
                    ldm4(r, sk + 2 * (p * 16 * AQ_ST + kk * 16 + kLane));
                    mma16(s[0][2 * p],     qa[0][kk], &r[0]);
                    mma16(s[0][2 * p + 1], qa[0][kk], &r[2]);
                    mma16(s[1][2 * p],     qa[1][kk], &r[0]);
                    mma16(s[1][2 * p + 1], qa[1][kk], &r[2]);
                }
            }

            // softmax per m-half
#pragma unroll
            for (int mh = 0; mh < 2; mh++) {
                const int rlo = m0 + rb + mh * 16 + g;
                const int rhi = rlo + 8;
                if (kb + 63 > m0 + rb + mh * 16) {
#pragma unroll
                    for (int nt = 0; nt < 8; nt++) {
                        int c0 = kb + nt * 8 + 2 * t;
                        s[mh][nt][0] = (c0     > rlo) ? -1e30f : s[mh][nt][0] * SC;
                        s[mh][nt][1] = (c0 + 1 > rlo) ? -1e30f : s[mh][nt][1] * SC;
                        s[mh][nt][2] = (c0     > rhi) ? -1e30f : s[mh][nt][2] * SC;
                        s[mh][nt][3] = (c0 + 1 > rhi) ? -1e30f : s[mh][nt][3] * SC;
                    }
                } else {
#pragma unroll
                    for (int nt = 0; nt < 8; nt++)
#pragma unroll
                        for (int j = 0; j < 4; j++) s[mh][nt][j] *= SC;
                }

                float tlo = -1e30f, thi = -1e30f;
#pragma unroll
                for (int nt = 0; nt < 8; nt++) {
                    tlo = fmaxf(tlo, fmaxf(s[mh][nt][0], s[mh][nt][1]));
                    thi = fmaxf(thi, fmaxf(s[mh][nt][2], s[mh][nt][3]));
                }
                tlo = fmaxf(tlo, __shfl_xor_sync(0xffffffff, tlo, 1));
                tlo = fmaxf(tlo, __shfl_xor_sync(0xffffffff, tlo, 2));
                thi = fmaxf(thi, __shfl_xor_sync(0xffffffff, thi, 1));
                thi = fmaxf(thi, __shfl_xor_sync(0xffffffff, thi, 2));

                float nmlo = fmaxf(mm[mh][0], tlo), nmhi = fmaxf(mm[mh][1], thi);
                float alo = ex2f(mm[mh][0] - nmlo), ahi = ex2f(mm[mh][1] - nmhi);
                mm[mh][0] = nmlo; mm[mh][1] = nmhi;

                float slo = 0.f, shi = 0.f;
#pragma unroll
                for (int nt = 0; nt < 8; nt++) {
                    s[mh][nt][0] = ex2f(s[mh][nt][0] - nmlo);
                    s[mh][nt][1] = ex2f(s[mh][nt][1] - nmlo);
                    s[mh][nt][2] = ex2f(s[mh][nt][2] - nmhi);
                    s[mh][nt][3] = ex2f(s[mh][nt][3] - nmhi);
                    slo += s[mh][nt][0] + s[mh][nt][1];
                    shi += s[mh][nt][2] + s[mh][nt][3];
                }
                slo += __shfl_xor_sync(0xffffffff, slo, 1);
                slo += __shfl_xor_sync(0xffffffff, slo, 2);
                shi += __shfl_xor_sync(0xffffffff, shi, 1);
                shi += __shfl_xor_sync(0xffffffff, shi, 2);
                ll[mh][0] = ll[mh][0] * alo + slo;
                ll[mh][1] = ll[mh][1] * ahi + shi;

#pragma unroll
                for (int nt = 0; nt < 8; nt++) {
                    o[mh][nt][0] *= alo; o[mh][nt][1] *= alo;
                    o[mh][nt][2] *= ahi; o[mh][nt][3] *= ahi;
                }
            }

            // O += P @ V  (P converted in-register; V frag shared)
#pragma unroll
            for (int kk = 0; kk < 4; kk++) {
                uint32_t pa0[4], pa1[4];
                pa0[0] = cvt2h(s[0][2*kk][0],   s[0][2*kk][1]);
                pa0[1] = cvt2h(s[0][2*kk][2],   s[0][2*kk][3]);
                pa0[2] = cvt2h(s[0][2*kk+1][0], s[0][2*kk+1][1]);
                pa0[3] = cvt2h(s[0][2*kk+1][2], s[0][2*kk+1][3]);
                pa1[0] = cvt2h(s[1][2*kk][0],   s[1][2*kk][1]);
                pa1[1] = cvt2h(s[1][2*kk][2],   s[1][2*kk][3]);
                pa1[2] = cvt2h(s[1][2*kk+1][0], s[1][2*kk+1][1]);
                pa1[3] = cvt2h(s[1][2*kk+1][2], s[1][2*kk+1][3]);
#pragma unroll
                for (int p = 0; p < 4; p++) {
                    uint32_t r[4];
                    ldm4t(r, sv + 2 * (kk * 16 * AQ_ST + p * 16 + vLane));
                    mma16(o[0][2 * p],     pa0, &r[0]);
                    mma16(o[0][2 * p + 1], pa0, &r[2]);
                    mma16(o[1][2 * p],     pa1, &r[0]);
                    mma16(o[1][2 * p + 1], pa1, &r[2]);
                }
            }
        }

        __syncthreads();
        if (tt + 2 < ntile) {
            attn_stage_kv_async(smh, tt & 1, kbp, vbp, (tt + 2) * 64, tid);
            CP_COMMIT();
            CP_WAIT1();
        } else {
            CP_WAIT0();
        }
        __syncthreads();
    }

    // epilogue: O /= l, f16, write to ctx (feeds fp16 proj GEMM)
    const int bidx = bh >> 4, h = bh & 15;
#pragma unroll
    for (int mh = 0; mh < 2; mh++) {
        const float ilo = 1.f / ll[mh][0], ihi = 1.f / ll[mh][1];
        const int rlo = m0 + rb + mh * 16 + g;
        const int rhi = rlo + 8;
        __half* clo = g_ctx + ((size_t)(bidx * SEQ + rlo)) * DMODEL + h * HDIM;
        __half* chi = g_ctx + ((size_t)(bidx * SEQ + rhi)) * DMODEL + h * HDIM;
#pragma unroll
        for (int nt = 0; nt < 8; nt++) {
            int c = nt * 8 + 2 * t;
            *(uint32_t*)(clo + c) = cvt2h(o[mh][nt][0] * ilo, o[mh][nt][1] * ilo);
            *(uint32_t*)(chi + c) = cvt2h(o[mh][nt][2] * ihi, o[mh][nt][3] * ihi);
        }
    }
}

// ---------------------------------------------------------------------------
extern "C" void kernel_launch(void* const* d_in, const int* in_sizes, int n_in,
                              void* d_out, int out_size)
{
    const float* x      = (const float*)d_in[0];   // [B,S,D]
    const float* w_qkv  = (const float*)d_in[1];   // [D, 3D]
    const float* b_qkv  = (const float*)d_in[2];   // [3D]
    const float* w_proj = (const float*)d_in[3];   // [D, D]
    const float* b_proj = (const float*)d_in[4];   // [D]
    float* out = (float*)d_out;                    // [B,S,D]

    __half *xh, *wqkvh, *wprojh, *ctxh;
    cudaGetSymbolAddress((void**)&xh, g_x);
    cudaGetSymbolAddress((void**)&wqkvh, g_wqkv);
    cudaGetSymbolAddress((void**)&wprojh, g_wproj);
    cudaGetSymbolAddress((void**)&ctxh, g_ctx);

    cudaFuncSetAttribute(gemm_tc, cudaFuncAttributeMaxDynamicSharedMemorySize, GEMM_SMEM);
    cudaFuncSetAttribute(attn_tc, cudaFuncAttributeMaxDynamicSharedMemorySize, ATT_SMEM);

    // 0) pre-convert all inputs to fp16 (one launch)
    to_half3_kernel<<<1184, 256>>>(
        (const float4*)x, (uint2*)xh, MROWS * DMODEL / 4,
        (const float4*)w_qkv, (uint2*)wqkvh, DMODEL * 3 * DMODEL / 4,
        (const float4*)w_proj, (uint2*)wprojh, DMODEL * DMODEL / 4);

    // 1) QKV projection -> g_q/g_k/g_v (fp16)
    {
        dim3 grid(3 * DMODEL / 128, MROWS / 128);  // (24, 32)
        gemm_tc<<<grid, 128, GEMM_SMEM>>>(xh, wqkvh, b_qkv, nullptr,
                                          MROWS, 3 * DMODEL, DMODEL, /*mode=*/1);
    }
    // 2) causal attention -> g_ctx (fp16)
    {
        dim3 grid(SEQ / 128, BH);                  // (16, 32)
        attn_tc<<<grid, 128, ATT_SMEM>>>();
    }
    // 3) output projection -> d_out (f32)
    {
        dim3 grid(DMODEL / 128, MROWS / 128);      // (8, 32)
        gemm_tc<<<grid, 128, GEMM_SMEM>>>(ctxh, wprojh, b_proj, out,
                                          MROWS, DMODEL, DMODEL, /*mode=*/0);
    }
    (void)in_sizes; (void)n_in; (void)out_size;
}

// round 16
// speedup vs baseline: 1.1858x; 1.1523x over previous
#include <cuda_runtime.h>
#include <cuda_fp16.h>
#include <cstdint>

// Problem constants
#define BATCH 2
#define SEQ   2048
#define DMODEL 1024
#define NHEAD 16
#define HDIM  64
#define BH    (BATCH*NHEAD)          // 32
#define MROWS (BATCH*SEQ)            // 4096

// Scratch (device globals: allocation-free per harness rules)
__device__ __half g_x[MROWS * DMODEL];
__device__ __half g_wqkv[DMODEL * 3 * DMODEL];
__device__ __half g_wproj[DMODEL * DMODEL];
__device__ __half g_q[BH * SEQ * HDIM];        // [bh][s][hd]
__device__ __half g_k[BH * SEQ * HDIM];
__device__ __half g_v[BH * SEQ * HDIM];
__device__ __half g_ctx[MROWS * DMODEL];       // [b*S+s][d]

// ---------------------------------------------------------------------------
// helpers
// ---------------------------------------------------------------------------
__device__ __forceinline__ uint32_t cvt2h(float lo, float hi) {  // pack f16x2
    uint32_t d;
    asm("cvt.rn.f16x2.f32 %0, %1, %2;" : "=r"(d) : "f"(hi), "f"(lo));
    return d;
}
__device__ __forceinline__ float ex2f(float x) {       // 2^x via MUFU
    float r;
    asm("ex2.approx.f32 %0, %1;" : "=f"(r) : "f"(x));
    return r;
}
__device__ __forceinline__ uint32_t smaddr(const void* p) {
    uint32_t a;
    asm("{ .reg .u64 t; cvta.to.shared.u64 t, %1; cvt.u32.u64 %0, t; }"
        : "=r"(a) : "l"(p));
    return a;
}

// async 16B copy gmem -> smem
__device__ __forceinline__ void cp16(void* smem_dst, const void* gsrc) {
    uint32_t d = smaddr(smem_dst);
    asm volatile("cp.async.cg.shared.global [%0], [%1], 16;" :: "r"(d), "l"(gsrc));
}
#define CP_COMMIT() asm volatile("cp.async.commit_group;" ::: "memory")
#define CP_WAIT1()  asm volatile("cp.async.wait_group 1;" ::: "memory")
#define CP_WAIT0()  asm volatile("cp.async.wait_group 0;" ::: "memory")

__device__ __forceinline__ void ldm4(uint32_t* r, uint32_t a) {
    asm volatile("ldmatrix.sync.aligned.m8n8.x4.shared.b16 {%0,%1,%2,%3}, [%4];"
        : "=r"(r[0]), "=r"(r[1]), "=r"(r[2]), "=r"(r[3]) : "r"(a));
}
__device__ __forceinline__ void ldm4t(uint32_t* r, uint32_t a) {
    asm volatile("ldmatrix.sync.aligned.m8n8.x4.trans.shared.b16 {%0,%1,%2,%3}, [%4];"
        : "=r"(r[0]), "=r"(r[1]), "=r"(r[2]), "=r"(r[3]) : "r"(a));
}

// mma m16n8k16 f16 inputs, f32 accum; D += A*B (C aliased to D)
__device__ __forceinline__ void mma16(float* d, const uint32_t* a, const uint32_t* b) {
    asm volatile(
        "mma.sync.aligned.m16n8k16.row.col.f32.f16.f16.f32 "
        "{%0,%1,%2,%3}, {%4,%5,%6,%7}, {%8,%9}, {%0,%1,%2,%3};\n"
        : "+f"(d[0]), "+f"(d[1]), "+f"(d[2]), "+f"(d[3])
        : "r"(a[0]), "r"(a[1]), "r"(a[2]), "r"(a[3]), "r"(b[0]), "r"(b[1]));
}

// ---------------------------------------------------------------------------
// f32 -> f16 pre-convert: all three inputs in ONE launch (grid-stride)
// ---------------------------------------------------------------------------
__global__ void to_half3_kernel(const float4* __restrict__ x,   uint2* __restrict__ xo,   int nx,
                                const float4* __restrict__ w1,  uint2* __restrict__ w1o,  int n1,
                                const float4* __restrict__ w2,  uint2* __restrict__ w2o,  int n2)
{
    const int stride = gridDim.x * blockDim.x;
    int i0 = blockIdx.x * blockDim.x + threadIdx.x;
    for (int i = i0; i < nx; i += stride) {
        float4 v = x[i];  uint2 o = { cvt2h(v.x, v.y), cvt2h(v.z, v.w) };  xo[i] = o;
    }
    for (int i = i0; i < n1; i += stride) {
        float4 v = w1[i]; uint2 o = { cvt2h(v.x, v.y), cvt2h(v.z, v.w) };  w1o[i] = o;
    }
    for (int i = i0; i < n2; i += stride) {
        float4 v = w2[i]; uint2 o = { cvt2h(v.x, v.y), cvt2h(v.z, v.w) };  w2o[i] = o;
    }
}

// ---------------------------------------------------------------------------
// fp16 mma.sync GEMM: C[M,N] = A[M,K] @ B[K,N] + bias (f32 accum).
// Tile 128x128x64, 128 threads (4 warps, 2m x 2n), warp tile 64x64.
// 3-stage cp.async ring; fragments via ldmatrix. 2 CTAs/SM.
// mode 0: write C f32 ; mode 1: scatter f16 q/k/v (QKV head layout)
// ---------------------------------------------------------------------------
#define GA_ST 72                               // A row stride (halfs)
#define GB_ST 136                              // B row stride (halfs)
#define G_STGH (128*GA_ST + 64*GB_ST)          // 17920 halfs per stage
#define GEMM_SMEM (3 * G_STGH * 2)             // 107,520 B

__device__ __forceinline__ void gemm_stage_async(
    __half* sm, int s, const __half* __restrict__ A, const __half* __restrict__ Bm,
    int m0, int n0, int kt, int K, int N, int tid)
{
    __half* As = sm + s * G_STGH;
    __half* Bs = As + 128 * GA_ST;
#pragma unroll
    for (int i = 0; i < 8; i++) {              // A: 1024 granules of 8 halfs
        int f = tid + i * 128;
        int row = f >> 3, c0 = (f & 7) * 8;
        cp16(&As[row * GA_ST + c0], A + (size_t)(m0 + row) * K + kt + c0);
    }
#pragma unroll
    for (int i = 0; i < 8; i++) {              // B: 1024 granules
        int f = tid + i * 128;
        int row = f >> 4, c0 = (f & 15) * 8;
        cp16(&Bs[row * GB_ST + c0], Bm + (size_t)(kt + row) * N + n0 + c0);
    }
}

__global__ __launch_bounds__(128, 2) void gemm_tc(
    const __half* __restrict__ A, const __half* __restrict__ Bm,
    const float* __restrict__ bias, float* __restrict__ C,
    int M, int N, int K, int mode)
{
    extern __shared__ __half smh[];

    const int tid  = threadIdx.x;
    const int wid  = tid >> 5;
    const int lane = tid & 31;
    const int g = lane >> 2, t = lane & 3;
    const int wm = wid >> 1, wn = wid & 1;
    const int m0 = blockIdx.y * 128;
    const int n0 = blockIdx.x * 128;

    // lane-dependent ldmatrix offsets (halfs)
    const int aLane = ((lane & 7) + ((lane >> 3) & 1) * 8) * GA_ST + (lane >> 4) * 8;
    const int bLane = ((lane & 7) + ((lane >> 3) & 1) * 8) * GB_ST + (lane >> 4) * 8;

    float acc[4][8][4];                        // warp tile 64x64
#pragma unroll
    for (int mt = 0; mt < 4; mt++)
#pragma unroll
        for (int nt = 0; nt < 8; nt++)
#pragma unroll
            for (int j = 0; j < 4; j++) acc[mt][nt][j] = 0.f;

    const int T = K / 64;   // 16
    gemm_stage_async(smh, 0, A, Bm, m0, n0, 0, K, N, tid);
    CP_COMMIT();
    gemm_stage_async(smh, 1, A, Bm, m0, n0, 64, K, N, tid);
    CP_COMMIT();

    for (int tt = 0; tt < T; tt++) {
        if (tt + 2 < T) CP_WAIT1(); else CP_WAIT0();
        __syncthreads();
        if (tt + 2 < T) {
            gemm_stage_async(smh, (tt + 2) % 3, A, Bm, m0, n0, (tt + 2) * 64, K, N, tid);
            CP_COMMIT();
        }
        const __half* As = smh + (tt % 3) * G_STGH;
        const __half* Bs = As + 128 * GA_ST;
        const uint32_t sa = smaddr(As);
        const uint32_t sb = smaddr(Bs);
#pragma unroll
        for (int kk = 0; kk < 4; kk++) {
            uint32_t av[4][4];
#pragma unroll
            for (int mt = 0; mt < 4; mt++)
                ldm4(av[mt], sa + 2 * ((wm * 64 + mt * 16) * GA_ST + kk * 16 + aLane));
            uint32_t bv[4][4];                 // [pair][4 regs] -> 2 n8 frags each
#pragma unroll
            for (int p = 0; p < 4; p++)
                ldm4t(bv[p], sb + 2 * (kk * 16 * GB_ST + wn * 64 + p * 16 + bLane));
#pragma unroll
            for (int mt = 0; mt < 4; mt++)
#pragma unroll
                for (int p = 0; p < 4; p++) {
                    mma16(acc[mt][2 * p],     av[mt], &bv[p][0]);
                    mma16(acc[mt][2 * p + 1], av[mt], &bv[p][2]);
                }
        }
    }

    // epilogue
#pragma unroll
    for (int mt = 0; mt < 4; mt++) {
        int r0 = m0 + wm * 64 + mt * 16 + g;
        int r1 = r0 + 8;
#pragma unroll
        for (int nt = 0; nt < 8; nt++) {
            int col = n0 + wn * 64 + nt * 8 + 2 * t;
            float2 b2 = *(const float2*)(bias + col);
            if (mode == 0) {
                float2 v0 = { acc[mt][nt][0] + b2.x, acc[mt][nt][1] + b2.y };
                float2 v1 = { acc[mt][nt][2] + b2.x, acc[mt][nt][3] + b2.y };
                *(float2*)(C + (size_t)r0 * N + col) = v0;
                *(float2*)(C + (size_t)r1 * N + col) = v1;
            } else {
                uint32_t h0 = cvt2h(acc[mt][nt][0] + b2.x, acc[mt][nt][1] + b2.y);
                uint32_t h1 = cvt2h(acc[mt][nt][2] + b2.x, acc[mt][nt][3] + b2.y);
                int part = col >> 10;
                int rr   = col & 1023;
                int h    = rr >> 6;
                int hd   = rr & 63;
                __half* dst = (part == 0) ? g_q : (part == 1) ? g_k : g_v;
                int b0i = r0 >> 11, s0 = r0 & 2047;
                int b1i = r1 >> 11, s1 = r1 & 2047;
                *(uint32_t*)(dst + ((size_t)(b0i * NHEAD + h) * SEQ + s0) * HDIM + hd) = h0;
                *(uint32_t*)(dst + ((size_t)(b1i * NHEAD + h) * SEQ + s1) * HDIM + hd) = h1;
            }
        }
    }
}

// ---------------------------------------------------------------------------
// fp16 tensor-core causal flash attention (round-11 structure).
// CTA: 128 threads (4 warps), BM=128, 32 rows/warp (2 m16 halves), BN=64.
// 2-stage KV ring; K/V fragments shared across both m-halves;
// P converted in-register (no smem round-trip).
// Grid (BH, SEQ/128) with reversed y: globally heaviest-first (LPT order).
// ---------------------------------------------------------------------------
#define AQ_ST 72                               // row stride (halfs)
#define ATT_QH  (128 * AQ_ST)
#define ATT_KVH (2 * 64 * AQ_ST)
#define ATT_SMEM ((ATT_QH + 2 * ATT_KVH) * 2)  // 55,296 B

__device__ __forceinline__ void attn_stage_kv_async(
    __half* base, int s, const __half* __restrict__ kbp, const __half* __restrict__ vbp,
    int kb, int tid)
{
    __half* Ks = base + ATT_QH + s * ATT_KVH;
    __half* Vs = Ks + 64 * AQ_ST;
#pragma unroll
    for (int i = 0; i < 4; i++) {
        int f = tid + i * 128;
        int row = f >> 3, c0 = (f & 7) * 8;
        cp16(&Ks[row * AQ_ST + c0], kbp + (size_t)(kb + row) * HDIM + c0);
        cp16(&Vs[row * AQ_ST + c0], vbp + (size_t)(kb + row) * HDIM + c0);
    }
}

__global__ __launch_bounds__(128, 2) void attn_tc()
{
    extern __shared__ __half smh[];
    __half* Qs = smh;

    const int tid  = threadIdx.x;
    const int wid  = tid >> 5;
    const int lane = tid & 31;
    const int g = lane >> 2, t = lane & 3;
    const int bh = blockIdx.x;                                    // head fastest
    const int m0 = ((int)gridDim.y - 1 - (int)blockIdx.y) * 128;  // heavy first (LPT)

    const __half* qb  = g_q + (size_t)bh * SEQ * HDIM;
    const __half* kbp = g_k + (size_t)bh * SEQ * HDIM;
    const __half* vbp = g_v + (size_t)bh * SEQ * HDIM;

    const int ntile = m0 / 64 + 2;
    const int rb = wid * 32;

    // lane-dependent ldmatrix offsets (halfs)
    const int qLane = ((lane & 7) + ((lane >> 3) & 1) * 8) * AQ_ST + (lane >> 4) * 8;
    const int kLane = ((lane & 7) + (lane >> 4) * 8) * AQ_ST + ((lane >> 3) & 1) * 8;
    const int vLane = qLane;

    // prologue: Q + KV tile0 in group 0, KV tile1 in group 1
#pragma unroll
    for (int i = 0; i < 8; i++) {
        int f = tid + i * 128;
        int row = f >> 3, c0 = (f & 7) * 8;
        cp16(&Qs[row * AQ_ST + c0], qb + (size_t)(m0 + row) * HDIM + c0);
    }
    attn_stage_kv_async(smh, 0, kbp, vbp, 0, tid);
    CP_COMMIT();
    attn_stage_kv_async(smh, 1, kbp, vbp, 64, tid);
    CP_COMMIT();
    CP_WAIT1();
    __syncthreads();

    // Q fragments: [mh][kk][4]
    uint32_t qa[2][4][4];
    {
        const uint32_t sq = smaddr(Qs);
#pragma unroll
        for (int mh = 0; mh < 2; mh++)
#pragma unroll
            for (int kk = 0; kk < 4; kk++)
                ldm4(qa[mh][kk], sq + 2 * ((rb + mh * 16) * AQ_ST + kk * 16 + qLane));
    }

    float o[2][8][4];
#pragma unroll
    for (int mh = 0; mh < 2; mh++)
#pragma unroll
        for (int nt = 0; nt < 8; nt++)
#pragma unroll
            for (int j = 0; j < 4; j++) o[mh][nt][j] = 0.f;
    float mm[2][2] = { {-1e30f, -1e30f}, {-1e30f, -1e30f} };
    float ll[2][2] = { {0.f, 0.f}, {0.f, 0.f} };

    const float SC = 0.125f * 1.44269504f;     // score scale, base-2 domain

    for (int tt = 0; tt < ntile; tt++) {
        const int kb = tt * 64;
        const __half* Kc = smh + ATT_QH + (tt & 1) * ATT_KVH;
        const __half* Vc = Kc + 64 * AQ_ST;

        if (kb <= m0 + rb + 31) {
            const uint32_t sk = smaddr(Kc);
            const uint32_t sv = smaddr(Vc);

            // S = Q @ K^T (warp: 32 x 64)
            float s[2][8][4];
#pragma unroll
            for (int mh = 0; mh < 2; mh++)
#pragma unroll
                for (int nt = 0; nt < 8; nt++)
#pragma unroll
                    for (int j = 0; j < 4; j++) s[mh][nt][j] = 0.f;
#pragma unroll
            for (int kk = 0; kk < 4; kk++) {
#pragma unroll
                for (int p = 0; p < 4; p++) {
                    uint32_t r[4];
                    ldm4(r, sk + 2 * (p * 16 * AQ_ST + kk * 16 + kLane));
                    mma16(s[0][2 * p],     qa[0][kk], &r[0]);
                    mma16(s[0][2 * p + 1], qa[0][kk], &r[2]);
                    mma16(s[1][2 * p],     qa[1][kk], &r[0]);
                    mma16(s[1][2 * p + 1], qa[1][kk], &r[2]);
                }
            }

            // softmax per m-half
#pragma unroll
            for (int mh = 0; mh < 2; mh++) {
                const int rlo = m0 + rb + mh * 16 + g;
                const int rhi = rlo + 8;
                if (kb + 63 > m0 + rb + mh * 16) {
#pragma unroll
                    for (int nt = 0; nt < 8; nt++) {
                        int c0 = kb + nt * 8 + 2 * t;
                        s[mh][nt][0] = (c0     > rlo) ? -1e30f : s[mh][nt][0] * SC;
                        s[mh][nt][1] = (c0 + 1 > rlo) ? -1e30f : s[mh][nt][1] * SC;
                        s[mh][nt][2] = (c0     > rhi) ? -1e30f : s[mh][nt][2] * SC;
                        s[mh][nt][3] = (c0 + 1 > rhi) ? -1e30f : s[mh][nt][3] * SC;
                    }
                } else {
#pragma unroll
                    for (int nt = 0; nt < 8; nt++)
#pragma unroll
                        for (int j = 0; j < 4; j++) s[mh][nt][j] *= SC;
                }

                float tlo = -1e30f, thi = -1e30f;
#pragma unroll
                for (int nt = 0; nt < 8; nt++) {
                    tlo = fmaxf(tlo, fmaxf(s[mh][nt][0], s[mh][nt][1]));
                    thi = fmaxf(thi, fmaxf(s[mh][nt][2], s[mh][nt][3]));
                }
                tlo = fmaxf(tlo, __shfl_xor_sync(0xffffffff, tlo, 1));
                tlo = fmaxf(tlo, __shfl_xor_sync(0xffffffff, tlo, 2));
                thi = fmaxf(thi, __shfl_xor_sync(0xffffffff, thi, 1));
                thi = fmaxf(thi, __shfl_xor_sync(0xffffffff, thi, 2));

                float nmlo = fmaxf(mm[mh][0], tlo), nmhi = fmaxf(mm[mh][1], thi);
                float alo = ex2f(mm[mh][0] - nmlo), ahi = ex2f(mm[mh][1] - nmhi);
                mm[mh][0] = nmlo; mm[mh][1] = nmhi;

                float slo = 0.f, shi = 0.f;
#pragma unroll
                for (int nt = 0; nt < 8; nt++) {
                    s[mh][nt][0] = ex2f(s[mh][nt][0] - nmlo);
                    s[mh][nt][1] = ex2f(s[mh][nt][1] - nmlo);
                    s[mh][nt][2] = ex2f(s[mh][nt][2] - nmhi);
                    s[mh][nt][3] = ex2f(s[mh][nt][3] - nmhi);
                    slo += s[mh][nt][0] + s[mh][nt][1];
                    shi += s[mh][nt][2] + s[mh][nt][3];
                }
                slo += __shfl_xor_sync(0xffffffff, slo, 1);
                slo += __shfl_xor_sync(0xffffffff, slo, 2);
                shi += __shfl_xor_sync(0xffffffff, shi, 1);
                shi += __shfl_xor_sync(0xffffffff, shi, 2);
                ll[mh][0] = ll[mh][0] * alo + slo;
                ll[mh][1] = ll[mh][1] * ahi + shi;

#pragma unroll
                for (int nt = 0; nt < 8; nt++) {
                    o[mh][nt][0] *= alo; o[mh][nt][1] *= alo;
                    o[mh][nt][2] *= ahi; o[mh][nt][3] *= ahi;
                }
            }

            // O += P @ V  (P converted in-register; V frag shared)
#pragma unroll
            for (int kk = 0; kk < 4; kk++) {
                uint32_t pa0[4], pa1[4];
                pa0[0] = cvt2h(s[0][2*kk][0],   s[0][2*kk][1]);
                pa0[1] = cvt2h(s[0][2*kk][2],   s[0][2*kk][3]);
                pa0[2] = cvt2h(s[0][2*kk+1][0], s[0][2*kk+1][1]);
                pa0[3] = cvt2h(s[0][2*kk+1][2], s[0][2*kk+1][3]);
                pa1[0] = cvt2h(s[1][2*kk][0],   s[1][2*kk][1]);
                pa1[1] = cvt2h(s[1][2*kk][2],   s[1][2*kk][3]);
                pa1[2] = cvt2h(s[1][2*kk+1][0], s[1][2*kk+1][1]);
                pa1[3] = cvt2h(s[1][2*kk+1][2], s[1][2*kk+1][3]);
#pragma unroll
                for (int p = 0; p < 4; p++) {
                    uint32_t r[4];
                    ldm4t(r, sv + 2 * (kk * 16 * AQ_ST + p * 16 + vLane));
                    mma16(o[0][2 * p],     pa0, &r[0]);
                    mma16(o[0][2 * p + 1], pa0, &r[2]);
                    mma16(o[1][2 * p],     pa1, &r[0]);
                    mma16(o[1][2 * p + 1], pa1, &r[2]);
                }
            }
        }

        __syncthreads();
        if (tt + 2 < ntile) {
            attn_stage_kv_async(smh, tt & 1, kbp, vbp, (tt + 2) * 64, tid);
            CP_COMMIT();
            CP_WAIT1();
        } else {
            CP_WAIT0();
        }
        __syncthreads();
    }

    // epilogue: O /= l, f16, write to ctx (feeds fp16 proj GEMM)
    const int bidx = bh >> 4, h = bh & 15;
#pragma unroll
    for (int mh = 0; mh < 2; mh++) {
        const float ilo = 1.f / ll[mh][0], ihi = 1.f / ll[mh][1];
        const int rlo = m0 + rb + mh * 16 + g;
        const int rhi = rlo + 8;
        __half* clo = g_ctx + ((size_t)(bidx * SEQ + rlo)) * DMODEL + h * HDIM;
        __half* chi = g_ctx + ((size_t)(bidx * SEQ + rhi)) * DMODEL + h * HDIM;
#pragma unroll
        for (int nt = 0; nt < 8; nt++) {
            int c = nt * 8 + 2 * t;
            *(uint32_t*)(clo + c) = cvt2h(o[mh][nt][0] * ilo, o[mh][nt][1] * ilo);
            *(uint32_t*)(chi + c) = cvt2h(o[mh][nt][2] * ihi, o[mh][nt][3] * ihi);
        }
    }
}

// ---------------------------------------------------------------------------
extern "C" void kernel_launch(void* const* d_in, const int* in_sizes, int n_in,
                              void* d_out, int out_size)
{
    const float* x      = (const float*)d_in[0];   // [B,S,D]
    const float* w_qkv  = (const float*)d_in[1];   // [D, 3D]
    const float* b_qkv  = (const float*)d_in[2];   // [3D]
    const float* w_proj = (const float*)d_in[3];   // [D, D]
    const float* b_proj = (const float*)d_in[4];   // [D]
    float* out = (float*)d_out;                    // [B,S,D]

    __half *xh, *wqkvh, *wprojh, *ctxh;
    cudaGetSymbolAddress((void**)&xh, g_x);
    cudaGetSymbolAddress((void**)&wqkvh, g_wqkv);
    cudaGetSymbolAddress((void**)&wprojh, g_wproj);
    cudaGetSymbolAddress((void**)&ctxh, g_ctx);

    cudaFuncSetAttribute(gemm_tc, cudaFuncAttributeMaxDynamicSharedMemorySize, GEMM_SMEM);
    cudaFuncSetAttribute(attn_tc, cudaFuncAttributeMaxDynamicSharedMemorySize, ATT_SMEM);

    // 0) pre-convert all inputs to fp16 (one launch)
    to_half3_kernel<<<1184, 256>>>(
        (const float4*)x, (uint2*)xh, MROWS * DMODEL / 4,
        (const float4*)w_qkv, (uint2*)wqkvh, DMODEL * 3 * DMODEL / 4,
        (const float4*)w_proj, (uint2*)wprojh, DMODEL * DMODEL / 4);

    // 1) QKV projection -> g_q/g_k/g_v (fp16)
    {
        dim3 grid(3 * DMODEL / 128, MROWS / 128);  // (24, 32)
        gemm_tc<<<grid, 128, GEMM_SMEM>>>(xh, wqkvh, b_qkv, nullptr,
                                          MROWS, 3 * DMODEL, DMODEL, /*mode=*/1);
    }
    // 2) causal attention -> g_ctx (fp16), globally heaviest-first
    {
        dim3 grid(BH, SEQ / 128);                  // (32, 16)
        attn_tc<<<grid, 128, ATT_SMEM>>>();
    }
    // 3) output projection -> d_out (f32)
    {
        dim3 grid(DMODEL / 128, MROWS / 128);      // (8, 32)
        gemm_tc<<<grid, 128, GEMM_SMEM>>>(ctxh, wprojh, b_proj, out,
                                          MROWS, DMODEL, DMODEL, /*mode=*/0);
    }
    (void)in_sizes; (void)n_in; (void)out_size;
}

// round 17
// speedup vs baseline: 1.1926x; 1.0058x over previous
#include <cuda_runtime.h>
#include <cuda_fp16.h>
#include <cstdint>

// Problem constants
#define BATCH 2
#define SEQ   2048
#define DMODEL 1024
#define NHEAD 16
#define HDIM  64
#define BH    (BATCH*NHEAD)          // 32
#define MROWS (BATCH*SEQ)            // 4096

// Scratch (device globals: allocation-free per harness rules)
__device__ __half g_x[MROWS * DMODEL];
__device__ __half g_wqkv[DMODEL * 3 * DMODEL];
__device__ __half g_wproj[DMODEL * DMODEL];
__device__ __half g_q[BH * SEQ * HDIM];        // [bh][s][hd]
__device__ __half g_k[BH * SEQ * HDIM];
__device__ __half g_v[BH * SEQ * HDIM];
__device__ __half g_ctx[MROWS * DMODEL];       // [b*S+s][d]

// ---------------------------------------------------------------------------
// helpers
// ---------------------------------------------------------------------------
__device__ __forceinline__ uint32_t cvt2h(float lo, float hi) {  // pack f16x2
    uint32_t d;
    asm("cvt.rn.f16x2.f32 %0, %1, %2;" : "=r"(d) : "f"(hi), "f"(lo));
    return d;
}
__device__ __forceinline__ float ex2f(float x) {       // 2^x via MUFU
    float r;
    asm("ex2.approx.f32 %0, %1;" : "=f"(r) : "f"(x));
    return r;
}
__device__ __forceinline__ uint32_t smaddr(const void* p) {
    uint32_t a;
    asm("{ .reg .u64 t; cvta.to.shared.u64 t, %1; cvt.u32.u64 %0, t; }"
        : "=r"(a) : "l"(p));
    return a;
}

// async 16B copy gmem -> smem
__device__ __forceinline__ void cp16(void* smem_dst, const void* gsrc) {
    uint32_t d = smaddr(smem_dst);
    asm volatile("cp.async.cg.shared.global [%0], [%1], 16;" :: "r"(d), "l"(gsrc));
}
#define CP_COMMIT() asm volatile("cp.async.commit_group;" ::: "memory")
#define CP_WAIT1()  asm volatile("cp.async.wait_group 1;" ::: "memory")
#define CP_WAIT0()  asm volatile("cp.async.wait_group 0;" ::: "memory")

__device__ __forceinline__ void ldm4(uint32_t* r, uint32_t a) {
    asm volatile("ldmatrix.sync.aligned.m8n8.x4.shared.b16 {%0,%1,%2,%3}, [%4];"
        : "=r"(r[0]), "=r"(r[1]), "=r"(r[2]), "=r"(r[3]) : "r"(a));
}
__device__ __forceinline__ void ldm4t(uint32_t* r, uint32_t a) {
    asm volatile("ldmatrix.sync.aligned.m8n8.x4.trans.shared.b16 {%0,%1,%2,%3}, [%4];"
        : "=r"(r[0]), "=r"(r[1]), "=r"(r[2]), "=r"(r[3]) : "r"(a));
}

// mma m16n8k16 f16 inputs, f32 accum; D += A*B (C aliased to D)
__device__ __forceinline__ void mma16(float* d, const uint32_t* a, const uint32_t* b) {
    asm volatile(
        "mma.sync.aligned.m16n8k16.row.col.f32.f16.f16.f32 "
        "{%0,%1,%2,%3}, {%4,%5,%6,%7}, {%8,%9}, {%0,%1,%2,%3};\n"
        : "+f"(d[0]), "+f"(d[1]), "+f"(d[2]), "+f"(d[3])
        : "r"(a[0]), "r"(a[1]), "r"(a[2]), "r"(a[3]), "r"(b[0]), "r"(b[1]));
}

// ---------------------------------------------------------------------------
// f32 -> f16 pre-convert: all three inputs in ONE launch (grid-stride)
// ---------------------------------------------------------------------------
__global__ void to_half3_kernel(const float4* __restrict__ x,   uint2* __restrict__ xo,   int nx,
                                const float4* __restrict__ w1,  uint2* __restrict__ w1o,  int n1,
                                const float4* __restrict__ w2,  uint2* __restrict__ w2o,  int n2)
{
    const int stride = gridDim.x * blockDim.x;
    int i0 = blockIdx.x * blockDim.x + threadIdx.x;
    for (int i = i0; i < nx; i += stride) {
        float4 v = x[i];  uint2 o = { cvt2h(v.x, v.y), cvt2h(v.z, v.w) };  xo[i] = o;
    }
    for (int i = i0; i < n1; i += stride) {
        float4 v = w1[i]; uint2 o = { cvt2h(v.x, v.y), cvt2h(v.z, v.w) };  w1o[i] = o;
    }
    for (int i = i0; i < n2; i += stride) {
        float4 v = w2[i]; uint2 o = { cvt2h(v.x, v.y), cvt2h(v.z, v.w) };  w2o[i] = o;
    }
}

// ---------------------------------------------------------------------------
// fp16 mma.sync GEMM: C[M,N] = A[M,K] @ B[K,N] + bias (f32 accum).
// Tile 128x128x64, 128 threads (4 warps, 2m x 2n), warp tile 64x64.
// 3-stage cp.async ring; A-fragments double-buffered across kk (B per-kk):
// A-side ldmatrix latency covered by the previous kk's 32 HMMA.
// mode 0: write C f32 ; mode 1: scatter f16 q/k/v (QKV head layout)
// ---------------------------------------------------------------------------
#define GA_ST 72                               // A row stride (halfs)
#define GB_ST 136                              // B row stride (halfs)
#define G_STGH (128*GA_ST + 64*GB_ST)          // 17920 halfs per stage
#define GEMM_SMEM (3 * G_STGH * 2)             // 107,520 B

__device__ __forceinline__ void gemm_stage_async(
    __half* sm, int s, const __half* __restrict__ A, const __half* __restrict__ Bm,
    int m0, int n0, int kt, int K, int N, int tid)
{
    __half* As = sm + s * G_STGH;
    __half* Bs = As + 128 * GA_ST;
#pragma unroll
    for (int i = 0; i < 8; i++) {              // A: 1024 granules of 8 halfs
        int f = tid + i * 128;
        int row = f >> 3, c0 = (f & 7) * 8;
        cp16(&As[row * GA_ST + c0], A + (size_t)(m0 + row) * K + kt + c0);
    }
#pragma unroll
    for (int i = 0; i < 8; i++) {              // B: 1024 granules
        int f = tid + i * 128;
        int row = f >> 4, c0 = (f & 15) * 8;
        cp16(&Bs[row * GB_ST + c0], Bm + (size_t)(kt + row) * N + n0 + c0);
    }
}

__global__ __launch_bounds__(128, 2) void gemm_tc(
    const __half* __restrict__ A, const __half* __restrict__ Bm,
    const float* __restrict__ bias, float* __restrict__ C,
    int M, int N, int K, int mode)
{
    extern __shared__ __half smh[];

    const int tid  = threadIdx.x;
    const int wid  = tid >> 5;
    const int lane = tid & 31;
    const int g = lane >> 2, t = lane & 3;
    const int wm = wid >> 1, wn = wid & 1;
    const int m0 = blockIdx.y * 128;
    const int n0 = blockIdx.x * 128;

    // lane-dependent ldmatrix offsets (halfs)
    const int aLane = ((lane & 7) + ((lane >> 3) & 1) * 8) * GA_ST + (lane >> 4) * 8;
    const int bLane = ((lane & 7) + ((lane >> 3) & 1) * 8) * GB_ST + (lane >> 4) * 8;

    float acc[4][8][4];                        // warp tile 64x64 (128 regs)
#pragma unroll
    for (int mt = 0; mt < 4; mt++)
#pragma unroll
        for (int nt = 0; nt < 8; nt++)
#pragma unroll
            for (int j = 0; j < 4; j++) acc[mt][nt][j] = 0.f;

    const int T = K / 64;   // 16
    gemm_stage_async(smh, 0, A, Bm, m0, n0, 0, K, N, tid);
    CP_COMMIT();
    gemm_stage_async(smh, 1, A, Bm, m0, n0, 64, K, N, tid);
    CP_COMMIT();

    for (int tt = 0; tt < T; tt++) {
        if (tt + 2 < T) CP_WAIT1(); else CP_WAIT0();
        __syncthreads();
        if (tt + 2 < T) {
            gemm_stage_async(smh, (tt + 2) % 3, A, Bm, m0, n0, (tt + 2) * 64, K, N, tid);
            CP_COMMIT();
        }
        const __half* As = smh + (tt % 3) * G_STGH;
        const __half* Bs = As + 128 * GA_ST;
        const uint32_t sa = smaddr(As);
        const uint32_t sb = smaddr(Bs);

        // A-fragments double-buffered across kk (+16 regs only)
        uint32_t av[2][4][4];
#pragma unroll
        for (int mt = 0; mt < 4; mt++)
            ldm4(av[0][mt], sa + 2 * ((wm * 64 + mt * 16) * GA_ST + aLane));

#pragma unroll
        for (int kk = 0; kk < 4; kk++) {
            if (kk < 3) {
#pragma unroll
                for (int mt = 0; mt < 4; mt++)
                    ldm4(av[(kk + 1) & 1][mt],
                         sa + 2 * ((wm * 64 + mt * 16) * GA_ST + (kk + 1) * 16 + aLane));
            }
            uint32_t bv[4][4];                 // [pair][4 regs] -> 2 n8 frags each
#pragma unroll
            for (int p = 0; p < 4; p++)
                ldm4t(bv[p], sb + 2 * (kk * 16 * GB_ST + wn * 64 + p * 16 + bLane));
#pragma unroll
            for (int mt = 0; mt < 4; mt++)
#pragma unroll
                for (int p = 0; p < 4; p++) {
                    mma16(acc[mt][2 * p],     av[kk & 1][mt], &bv[p][0]);
                    mma16(acc[mt][2 * p + 1], av[kk & 1][mt], &bv[p][2]);
                }
        }
    }

    // epilogue
#pragma unroll
    for (int mt = 0; mt < 4; mt++) {
        int r0 = m0 + wm * 64 + mt * 16 + g;
        int r1 = r0 + 8;
#pragma unroll
        for (int nt = 0; nt < 8; nt++) {
            int col = n0 + wn * 64 + nt * 8 + 2 * t;
            float2 b2 = *(const float2*)(bias + col);
            if (mode == 0) {
                float2 v0 = { acc[mt][nt][0] + b2.x, acc[mt][nt][1] + b2.y };
                float2 v1 = { acc[mt][nt][2] + b2.x, acc[mt][nt][3] + b2.y };
                *(float2*)(C + (size_t)r0 * N + col) = v0;
                *(float2*)(C + (size_t)r1 * N + col) = v1;
            } else {
                uint32_t h0 = cvt2h(acc[mt][nt][0] + b2.x, acc[mt][nt][1] + b2.y);
                uint32_t h1 = cvt2h(acc[mt][nt][2] + b2.x, acc[mt][nt][3] + b2.y);
                int part = col >> 10;
                int rr   = col & 1023;
                int h    = rr >> 6;
                int hd   = rr & 63;
                __half* dst = (part == 0) ? g_q : (part == 1) ? g_k : g_v;
                int b0i = r0 >> 11, s0 = r0 & 2047;
                int b1i = r1 >> 11, s1 = r1 & 2047;
                *(uint32_t*)(dst + ((size_t)(b0i * NHEAD + h) * SEQ + s0) * HDIM + hd) = h0;
                *(uint32_t*)(dst + ((size_t)(b1i * NHEAD + h) * SEQ + s1) * HDIM + hd) = h1;
            }
        }
    }
}

// ---------------------------------------------------------------------------
// fp16 tensor-core causal flash attention (round-16 proven version).
// CTA: 128 threads (4 warps), BM=128, 32 rows/warp (2 m16 halves), BN=64.
// 2-stage KV ring; K/V fragments shared across both m-halves;
// P converted in-register. Grid (BH, SEQ/128), reversed y: LPT order.
// ---------------------------------------------------------------------------
#define AQ_ST 72                               // row stride (halfs)
#define ATT_QH  (128 * AQ_ST)
#define ATT_KVH (2 * 64 * AQ_ST)
#define ATT_SMEM ((ATT_QH + 2 * ATT_KVH) * 2)  // 55,296 B

__device__ __forceinline__ void attn_stage_kv_async(
    __half* base, int s, const __half* __restrict__ kbp, const __half* __restrict__ vbp,
    int kb, int tid)
{
    __half* Ks = base + ATT_QH + s * ATT_KVH;
    __half* Vs = Ks + 64 * AQ_ST;
#pragma unroll
    for (int i = 0; i < 4; i++) {
        int f = tid + i * 128;
        int row = f >> 3, c0 = (f & 7) * 8;
        cp16(&Ks[row * AQ_ST + c0], kbp + (size_t)(kb + row) * HDIM + c0);
        cp16(&Vs[row * AQ_ST + c0], vbp + (size_t)(kb + row) * HDIM + c0);
    }
}

__global__ __launch_bounds__(128, 2) void attn_tc()
{
    extern __shared__ __half smh[];
    __half* Qs = smh;

    const int tid  = threadIdx.x;
    const int wid  = tid >> 5;
    const int lane = tid & 31;
    const int g = lane >> 2, t = lane & 3;
    const int bh = blockIdx.x;                                    // head fastest
    const int m0 = ((int)gridDim.y - 1 - (int)blockIdx.y) * 128;  // heavy first (LPT)

    const __half* qb  = g_q + (size_t)bh * SEQ * HDIM;
    const __half* kbp = g_k + (size_t)bh * SEQ * HDIM;
    const __half* vbp = g_v + (size_t)bh * SEQ * HDIM;

    const int ntile = m0 / 64 + 2;
    const int rb = wid * 32;

    // lane-dependent ldmatrix offsets (halfs)
    const int qLane = ((lane & 7) + ((lane >> 3) & 1) * 8) * AQ_ST + (lane >> 4) * 8;
    const int kLane = ((lane & 7) + (lane >> 4) * 8) * AQ_ST + ((lane >> 3) & 1) * 8;
    const int vLane = qLane;

    // prologue: Q + KV tile0 in group 0, KV tile1 in group 1
#pragma unroll
    for (int i = 0; i < 8; i++) {
        int f = tid + i * 128;
        int row = f >> 3, c0 = (f & 7) * 8;
        cp16(&Qs[row * AQ_ST + c0], qb + (size_t)(m0 + row) * HDIM + c0);
    }
    attn_stage_kv_async(smh, 0, kbp, vbp, 0, tid);
    CP_COMMIT();
    attn_stage_kv_async(smh, 1, kbp, vbp, 64, tid);
    CP_COMMIT();
    CP_WAIT1();
    __syncthreads();

    // Q fragments: [mh][kk][4]
    uint32_t qa[2][4][4];
    {
        const uint32_t sq = smaddr(Qs);
#pragma unroll
        for (int mh = 0; mh < 2; mh++)
#pragma unroll
            for (int kk = 0; kk < 4; kk++)
                ldm4(qa[mh][kk], sq + 2 * ((rb + mh * 16) * AQ_ST + kk * 16 + qLane));
    }

    float o[2][8][4];
#pragma unroll
    for (int mh = 0; mh < 2; mh++)
#pragma unroll
        for (int nt = 0; nt < 8; nt++)
#pragma unroll
            for (int j = 0; j < 4; j++) o[mh][nt][j] = 0.f;
    float mm[2][2] = { {-1e30f, -1e30f}, {-1e30f, -1e30f} };
    float ll[2][2] = { {0.f, 0.f}, {0.f, 0.f} };

    const float SC = 0.125f * 1.44269504f;     // score scale, base-2 domain

    for (int tt = 0; tt < ntile; tt++) {
        const int kb = tt * 64;
        const __half* Kc = smh + ATT_QH + (tt & 1) * ATT_KVH;
        const __half* Vc = Kc + 64 * AQ_ST;

        if (kb <= m0 + rb + 31) {
            const uint32_t sk = smaddr(Kc);
            const uint32_t sv = smaddr(Vc);

            // S = Q @ K^T (warp: 32 x 64)
            float s[2][8][4];
#pragma unroll
            for (int mh = 0; mh < 2; mh++)
#pragma unroll
                for (int nt = 0; nt < 8; nt++)
#pragma unroll
                    for (int j = 0; j < 4; j++) s[mh][nt][j] = 0.f;
#pragma unroll
            for (int kk = 0; kk < 4; kk++) {
#pragma unroll
                for (int p = 0; p < 4; p++) {
                    uint32_t r[4];
                    ldm4(r, sk + 2 * (p * 16 * AQ_ST + kk * 16 + kLane));
                    mma16(s[0][2 * p],     qa[0][kk], &r[0]);
                    mma16(s[0][2 * p + 1], qa[0][kk], &r[2]);
                    mma16(s[1][2 * p],     qa[1][kk], &r[0]);
                    mma16(s[1][2 * p + 1], qa[1][kk], &r[2]);
                }
            }

            // softmax per m-half
#pragma unroll
            for (int mh = 0; mh < 2; mh++) {
                const int rlo = m0 + rb + mh * 16 + g;
                const int rhi = rlo + 8;
                if (kb + 63 > m0 + rb + mh * 16) {
#pragma unroll
                    for (int nt = 0; nt < 8; nt++) {
                        int c0 = kb + nt * 8 + 2 * t;
                        s[mh][nt][0] = (c0     > rlo) ? -1e30f : s[mh][nt][0] * SC;
                        s[mh][nt][1] = (c0 + 1 > rlo) ? -1e30f : s[mh][nt][1] * SC;
                        s[mh][nt][2] = (c0     > rhi) ? -1e30f : s[mh][nt][2] * SC;
                        s[mh][nt][3] = (c0 + 1 > rhi) ? -1e30f : s[mh][nt][3] * SC;
                    }
                } else {
#pragma unroll
                    for (int nt = 0; nt < 8; nt++)
#pragma unroll
                        for (int j = 0; j < 4; j++) s[mh][nt][j] *= SC;
                }

                float tlo = -1e30f, thi = -1e30f;
#pragma unroll
                for (int nt = 0; nt < 8; nt++) {
                    tlo = fmaxf(tlo, fmaxf(s[mh][nt][0], s[mh][nt][1]));
                    thi = fmaxf(thi, fmaxf(s[mh][nt][2], s[mh][nt][3]));
                }
                tlo = fmaxf(tlo, __shfl_xor_sync(0xffffffff, tlo, 1));
                tlo = fmaxf(tlo, __shfl_xor_sync(0xffffffff, tlo, 2));
                thi = fmaxf(thi, __shfl_xor_sync(0xffffffff, thi, 1));
                thi = fmaxf(thi, __shfl_xor_sync(0xffffffff, thi, 2));

                float nmlo = fmaxf(mm[mh][0], tlo), nmhi = fmaxf(mm[mh][1], thi);
                float alo = ex2f(mm[mh][0] - nmlo), ahi = ex2f(mm[mh][1] - nmhi);
                mm[mh][0] = nmlo; mm[mh][1] = nmhi;

                float slo = 0.f, shi = 0.f;
#pragma unroll
                for (int nt = 0; nt < 8; nt++) {
                    s[mh][nt][0] = ex2f(s[mh][nt][0] - nmlo);
                    s[mh][nt][1] = ex2f(s[mh][nt][1] - nmlo);
                    s[mh][nt][2] = ex2f(s[mh][nt][2] - nmhi);
                    s[mh][nt][3] = ex2f(s[mh][nt][3] - nmhi);
                    slo += s[mh][nt][0] + s[mh][nt][1];
                    shi += s[mh][nt][2] + s[mh][nt][3];
                }
                slo += __shfl_xor_sync(0xffffffff, slo, 1);
                slo += __shfl_xor_sync(0xffffffff, slo, 2);
                shi += __shfl_xor_sync(0xffffffff, shi, 1);
                shi += __shfl_xor_sync(0xffffffff, shi, 2);
                ll[mh][0] = ll[mh][0] * alo + slo;
                ll[mh][1] = ll[mh][1] * ahi + shi;

#pragma unroll
                for (int nt = 0; nt < 8; nt++) {
                    o[mh][nt][0] *= alo; o[mh][nt][1] *= alo;
                    o[mh][nt][2] *= ahi; o[mh][nt][3] *= ahi;
                }
            }

            // O += P @ V  (P converted in-register; V frag shared)
#pragma unroll
            for (int kk = 0; kk < 4; kk++) {
                uint32_t pa0[4], pa1[4];
                pa0[0] = cvt2h(s[0][2*kk][0],   s[0][2*kk][1]);
                pa0[1] = cvt2h(s[0][2*kk][2],   s[0][2*kk][3]);
                pa0[2] = cvt2h(s[0][2*kk+1][0], s[0][2*kk+1][1]);
                pa0[3] = cvt2h(s[0][2*kk+1][2], s[0][2*kk+1][3]);
                pa1[0] = cvt2h(s[1][2*kk][0],   s[1][2*kk][1]);
                pa1[1] = cvt2h(s[1][2*kk][2],   s[1][2*kk][3]);
                pa1[2] = cvt2h(s[1][2*kk+1][0], s[1][2*kk+1][1]);
                pa1[3] = cvt2h(s[1][2*kk+1][2], s[1][2*kk+1][3]);
#pragma unroll
                for (int p = 0; p < 4; p++) {
                    uint32_t r[4];
                    ldm4t(r, sv + 2 * (kk * 16 * AQ_ST + p * 16 + vLane));
                    mma16(o[0][2 * p],     pa0, &r[0]);
                    mma16(o[0][2 * p + 1], pa0, &r[2]);
                    mma16(o[1][2 * p],     pa1, &r[0]);
                    mma16(o[1][2 * p + 1], pa1, &r[2]);
                }
            }
        }

        __syncthreads();
        if (tt + 2 < ntile) {
            attn_stage_kv_async(smh, tt & 1, kbp, vbp, (tt + 2) * 64, tid);
            CP_COMMIT();
            CP_WAIT1();
        } else {
            CP_WAIT0();
        }
        __syncthreads();
    }

    // epilogue: O /= l, f16, write to ctx (feeds fp16 proj GEMM)
    const int bidx = bh >> 4, h = bh & 15;
#pragma unroll
    for (int mh = 0; mh < 2; mh++) {
        const float ilo = 1.f / ll[mh][0], ihi = 1.f / ll[mh][1];
        const int rlo = m0 + rb + mh * 16 + g;
        const int rhi = rlo + 8;
        __half* clo = g_ctx + ((size_t)(bidx * SEQ + rlo)) * DMODEL + h * HDIM;
        __half* chi = g_ctx + ((size_t)(bidx * SEQ + rhi)) * DMODEL + h * HDIM;
#pragma unroll
        for (int nt = 0; nt < 8; nt++) {
            int c = nt * 8 + 2 * t;
            *(uint32_t*)(clo + c) = cvt2h(o[mh][nt][0] * ilo, o[mh][nt][1] * ilo);
            *(uint32_t*)(chi + c) = cvt2h(o[mh][nt][2] * ihi, o[mh][nt][3] * ihi);
        }
    }
}

// ---------------------------------------------------------------------------
extern "C" void kernel_launch(void* const* d_in, const int* in_sizes, int n_in,
                              void* d_out, int out_size)
{
    const float* x      = (const float*)d_in[0];   // [B,S,D]
    const float* w_qkv  = (const float*)d_in[1];   // [D, 3D]
    const float* b_qkv  = (const float*)d_in[2];   // [3D]
    const float* w_proj = (const float*)d_in[3];   // [D, D]
    const float* b_proj = (const float*)d_in[4];   // [D]
    float* out = (float*)d_out;                    // [B,S,D]

    __half *xh, *wqkvh, *wprojh, *ctxh;
    cudaGetSymbolAddress((void**)&xh, g_x);
    cudaGetSymbolAddress((void**)&wqkvh, g_wqkv);
    cudaGetSymbolAddress((void**)&wprojh, g_wproj);
    cudaGetSymbolAddress((void**)&ctxh, g_ctx);

    cudaFuncSetAttribute(gemm_tc, cudaFuncAttributeMaxDynamicSharedMemorySize, GEMM_SMEM);
    cudaFuncSetAttribute(attn_tc, cudaFuncAttributeMaxDynamicSharedMemorySize, ATT_SMEM);

    // 0) pre-convert all inputs to fp16 (one launch)
    to_half3_kernel<<<1184, 256>>>(
        (const float4*)x, (uint2*)xh, MROWS * DMODEL / 4,
        (const float4*)w_qkv, (uint2*)wqkvh, DMODEL * 3 * DMODEL / 4,
        (const float4*)w_proj, (uint2*)wprojh, DMODEL * DMODEL / 4);

    // 1) QKV projection -> g_q/g_k/g_v (fp16)
    {
        dim3 grid(3 * DMODEL / 128, MROWS / 128);  // (24, 32)
        gemm_tc<<<grid, 128, GEMM_SMEM>>>(xh, wqkvh, b_qkv, nullptr,
                                          MROWS, 3 * DMODEL, DMODEL, /*mode=*/1);
    }
    // 2) causal attention -> g_ctx (fp16), globally heaviest-first
    {
        dim3 grid(BH, SEQ / 128);                  // (32, 16)
        attn_tc<<<grid, 128, ATT_SMEM>>>();
    }
    // 3) output projection -> d_out (f32)
    {
        dim3 grid(DMODEL / 128, MROWS / 128);      // (8, 32)
        gemm_tc<<<grid, 128, GEMM_SMEM>>>(ctxh, wprojh, b_proj, out,
                                          MROWS, DMODEL, DMODEL, /*mode=*/0);
    }
    (void)in_sizes; (void)n_in; (void)out_size;
}